// round 17
// baseline (speedup 1.0000x reference)
#include <cuda_runtime.h>
#include <math.h>
#include <stdint.h>

#define NN 100000   // nodes
#define NF 128      // in feats
#define NH 256      // hidden
#define NC 40       // classes
#define NE 800000   // edges
#define NB ((NN + 255) / 256)   // 391 scan blocks

// ---------------- scratch (static device memory; no allocs) ----------------
__device__ float  g_dinv [NN];
__device__ int    g_cnt  [NN];
__device__ int    g_off  [NN];
__device__ int    g_cur  [NN];
__device__ int    g_adj  [NE];
__device__ int    g_bsum [NB + 1];
__device__ int    g_boff [NB + 1];
__device__ float4 g_aggx4[NN * NF / 4];
__device__ float4 g_h4   [NN * NH / 4];
__device__ float4 g_g4   [NN * NC / 4];

// ---------------- base-target PTX helpers ----------------
__device__ __forceinline__ void split_tf32(float a, uint32_t& hi, uint32_t& lo) {
    asm("cvt.rna.tf32.f32 %0, %1;" : "=r"(hi) : "f"(a));
    float r = a - __uint_as_float(hi);
    asm("cvt.rna.tf32.f32 %0, %1;" : "=r"(lo) : "f"(r));
}
__device__ __forceinline__ void mma16n8k8(float* d, const uint32_t* a, const uint32_t* b) {
    asm volatile(
        "mma.sync.aligned.m16n8k8.row.col.f32.tf32.tf32.f32 "
        "{%0,%1,%2,%3}, {%4,%5,%6,%7}, {%8,%9}, {%0,%1,%2,%3};"
        : "+f"(d[0]), "+f"(d[1]), "+f"(d[2]), "+f"(d[3])
        : "r"(a[0]), "r"(a[1]), "r"(a[2]), "r"(a[3]), "r"(b[0]), "r"(b[1]));
}

// ---------------- CSR build (g_cnt zeroed via cudaMemsetAsync) -------------
__global__ void k_hist(const int* __restrict__ dst) {
    int e = blockIdx.x * blockDim.x + threadIdx.x;
    if (e < NE) atomicAdd(&g_cnt[dst[e]], 1);
}
__global__ void k_bsum() {
    __shared__ int sh[256];
    int t = threadIdx.x, i = blockIdx.x * 256 + t;
    int v = (i < NN) ? g_cnt[i] : 0;
    sh[t] = v; __syncthreads();
    for (int off = 128; off; off >>= 1) {
        if (t < off) sh[t] += sh[t + off];
        __syncthreads();
    }
    if (t == 0) g_bsum[blockIdx.x] = sh[0];
}
__global__ void k_bscan() {
    __shared__ int sh[512];
    int t = threadIdx.x;
    int v = (t < NB) ? g_bsum[t] : 0;
    sh[t] = v; __syncthreads();
    for (int off = 1; off < 512; off <<= 1) {
        int tv = (t >= off) ? sh[t - off] : 0;
        __syncthreads();
        sh[t] += tv;
        __syncthreads();
    }
    if (t < NB) g_boff[t] = sh[t] - v;
}
// per-block exclusive scan + base => offsets/cursors; dinv fused in
__global__ void k_offsets() {
    __shared__ int sh[256];
    int t = threadIdx.x, i = blockIdx.x * 256 + t;
    int v = (i < NN) ? g_cnt[i] : 0;
    sh[t] = v; __syncthreads();
    for (int off = 1; off < 256; off <<= 1) {
        int tv = (t >= off) ? sh[t - off] : 0;
        __syncthreads();
        sh[t] += tv;
        __syncthreads();
    }
    if (i < NN) {
        int o = g_boff[blockIdx.x] + sh[t] - v;
        g_off[i] = o;
        g_cur[i] = o;
        g_dinv[i] = rsqrtf((float)(v + 1));   // +1 self-loop
    }
}
__global__ void k_fill(const int* __restrict__ src, const int* __restrict__ dst) {
    int e = blockIdx.x * blockDim.x + threadIdx.x;
    if (e >= NE) return;
    int d = dst[e];
    int p = atomicAdd(&g_cur[d], 1);
    g_adj[p] = src[e];
}

// ---------------- layer-1 gather: aggx = A~ x (warp per node) --------------
__global__ void k_gather_x(const float* __restrict__ x) {
    int t = blockIdx.x * blockDim.x + threadIdx.x;
    int w = t >> 5, lane = t & 31;
    if (w >= NN) return;
    const float4* x4 = (const float4*)x;
    float di = g_dinv[w];
    float4 a = x4[(size_t)w * 32 + lane];
    float s2 = di * di;
    float ax = a.x * s2, ay = a.y * s2, az = a.z * s2, aw = a.w * s2;
    int beg = g_off[w], n = g_cnt[w];
    int j = 0;
    for (; j + 4 <= n; j += 4) {
        int s0 = g_adj[beg + j], s1 = g_adj[beg + j + 1];
        int s2i = g_adj[beg + j + 2], s3 = g_adj[beg + j + 3];
        float n0 = di * g_dinv[s0], n1 = di * g_dinv[s1];
        float n2 = di * g_dinv[s2i], n3 = di * g_dinv[s3];
        float4 v0 = x4[(size_t)s0 * 32 + lane];
        float4 v1 = x4[(size_t)s1 * 32 + lane];
        float4 v2 = x4[(size_t)s2i * 32 + lane];
        float4 v3 = x4[(size_t)s3 * 32 + lane];
        ax += v0.x * n0 + v1.x * n1 + v2.x * n2 + v3.x * n3;
        ay += v0.y * n0 + v1.y * n1 + v2.y * n2 + v3.y * n3;
        az += v0.z * n0 + v1.z * n1 + v2.z * n2 + v3.z * n3;
        aw += v0.w * n0 + v1.w * n1 + v2.w * n2 + v3.w * n3;
    }
    for (; j < n; j++) {
        int s = g_adj[beg + j];
        float nr = di * g_dinv[s];
        float4 v = x4[(size_t)s * 32 + lane];
        ax += v.x * nr; ay += v.y * nr; az += v.z * nr; aw += v.w * nr;
    }
    g_aggx4[(size_t)w * 32 + lane] = make_float4(ax, ay, az, aw);
}

// ---------------- GEMM1: 128x128 tile, double-buffered, tf32x3 -------------
// 8 warps as 4(m) x 2(n); warp tile 32x64 (2 m-frags x 8 n-frags).
#define STR 36
#define ABUF (128 * STR)
__global__ void __launch_bounds__(256)
k_mma_gemm128(const float* __restrict__ A, const float* __restrict__ Bw,
              const float* __restrict__ bias, float* __restrict__ C, int M) {
    const int N = NH, K = NF;
    extern __shared__ float sm[];
    float* As_hi = sm;                       // [2][128*STR]
    float* As_lo = As_hi + 2 * ABUF;
    float* Bs_hi = As_lo + 2 * ABUF;         // [2][128*STR]
    float* Bs_lo = Bs_hi + 2 * ABUF;

    const int tid = threadIdx.x;
    const int wid = tid >> 5, lid = tid & 31;
    const int wm = wid & 3, wn = wid >> 2;
    const int g = lid >> 2, tig = lid & 3;
    const int mBase = blockIdx.y * 128;
    const int colBase = blockIdx.x * 128;

    float d[2][8][4];
#pragma unroll
    for (int a = 0; a < 2; a++)
#pragma unroll
        for (int b = 0; b < 8; b++)
#pragma unroll
            for (int c = 0; c < 4; c++) d[a][b][c] = 0.f;

    const int KB = K >> 5;   // 4
    float4 ra[4], rb4[4];
    // prefetch chunk 0
#pragma unroll
    for (int u = 0; u < 4; u++) {
        int i = tid + u * 256;
        int m = i >> 3, q = (i & 7) << 2;
        int gm = mBase + m;
        ra[u] = (gm < M) ? *(const float4*)&A[(size_t)gm * K + q]
                         : make_float4(0.f, 0.f, 0.f, 0.f);
    }
#pragma unroll
    for (int u = 0; u < 4; u++) {
        int i = tid + u * 256;
        int kc = i >> 5, n4 = (i & 31) << 2;
        rb4[u] = *(const float4*)&Bw[(size_t)kc * N + colBase + n4];
    }

    for (int kb = 0; kb < KB; kb++) {
        const int bo = kb & 1;
        float* Ah = As_hi + bo * ABUF;
        float* Al = As_lo + bo * ABUF;
        float* Bh = Bs_hi + bo * ABUF;
        float* Bl = Bs_lo + bo * ABUF;
#pragma unroll
        for (int u = 0; u < 4; u++) {
            int i = tid + u * 256;
            int m = i >> 3, q = (i & 7) << 2;
            uint32_t h0, l0, h1, l1, h2, l2, h3, l3;
            split_tf32(ra[u].x, h0, l0); split_tf32(ra[u].y, h1, l1);
            split_tf32(ra[u].z, h2, l2); split_tf32(ra[u].w, h3, l3);
            float* ph = Ah + m * STR + q;
            float* pl = Al + m * STR + q;
            ph[0] = __uint_as_float(h0); ph[1] = __uint_as_float(h1);
            ph[2] = __uint_as_float(h2); ph[3] = __uint_as_float(h3);
            pl[0] = __uint_as_float(l0); pl[1] = __uint_as_float(l1);
            pl[2] = __uint_as_float(l2); pl[3] = __uint_as_float(l3);
        }
#pragma unroll
        for (int u = 0; u < 4; u++) {
            int i = tid + u * 256;
            int kc = i >> 5, n4 = (i & 31) << 2;
            uint32_t h0, l0, h1, l1, h2, l2, h3, l3;
            split_tf32(rb4[u].x, h0, l0); split_tf32(rb4[u].y, h1, l1);
            split_tf32(rb4[u].z, h2, l2); split_tf32(rb4[u].w, h3, l3);
            Bh[(n4 + 0) * STR + kc] = __uint_as_float(h0);
            Bh[(n4 + 1) * STR + kc] = __uint_as_float(h1);
            Bh[(n4 + 2) * STR + kc] = __uint_as_float(h2);
            Bh[(n4 + 3) * STR + kc] = __uint_as_float(h3);
            Bl[(n4 + 0) * STR + kc] = __uint_as_float(l0);
            Bl[(n4 + 1) * STR + kc] = __uint_as_float(l1);
            Bl[(n4 + 2) * STR + kc] = __uint_as_float(l2);
            Bl[(n4 + 3) * STR + kc] = __uint_as_float(l3);
        }
        __syncthreads();
        // prefetch next chunk (overlaps MMA below)
        if (kb + 1 < KB) {
            const int kpos = (kb + 1) << 5;
#pragma unroll
            for (int u = 0; u < 4; u++) {
                int i = tid + u * 256;
                int m = i >> 3, q = (i & 7) << 2;
                int gm = mBase + m;
                ra[u] = (gm < M) ? *(const float4*)&A[(size_t)gm * K + kpos + q]
                                 : make_float4(0.f, 0.f, 0.f, 0.f);
            }
#pragma unroll
            for (int u = 0; u < 4; u++) {
                int i = tid + u * 256;
                int kc = i >> 5, n4 = (i & 31) << 2;
                rb4[u] = *(const float4*)&Bw[(size_t)(kpos + kc) * N + colBase + n4];
            }
        }
#pragma unroll
        for (int ks = 0; ks < 4; ks++) {
            const int k0 = (ks << 3) + tig;
            uint32_t ah[2][4], al[2][4], bh[8][2], bl[8][2];
#pragma unroll
            for (int im = 0; im < 2; im++) {
                int r0 = (wm * 32 + im * 16 + g) * STR;
                ah[im][0] = __float_as_uint(Ah[r0 + k0]);
                ah[im][1] = __float_as_uint(Ah[r0 + 8 * STR + k0]);
                ah[im][2] = __float_as_uint(Ah[r0 + k0 + 4]);
                ah[im][3] = __float_as_uint(Ah[r0 + 8 * STR + k0 + 4]);
                al[im][0] = __float_as_uint(Al[r0 + k0]);
                al[im][1] = __float_as_uint(Al[r0 + 8 * STR + k0]);
                al[im][2] = __float_as_uint(Al[r0 + k0 + 4]);
                al[im][3] = __float_as_uint(Al[r0 + 8 * STR + k0 + 4]);
            }
#pragma unroll
            for (int in_ = 0; in_ < 8; in_++) {
                int n0 = (wn * 64 + in_ * 8 + g) * STR;
                bh[in_][0] = __float_as_uint(Bh[n0 + k0]);
                bh[in_][1] = __float_as_uint(Bh[n0 + k0 + 4]);
                bl[in_][0] = __float_as_uint(Bl[n0 + k0]);
                bl[in_][1] = __float_as_uint(Bl[n0 + k0 + 4]);
            }
#pragma unroll
            for (int im = 0; im < 2; im++)
#pragma unroll
                for (int in_ = 0; in_ < 8; in_++)
                    mma16n8k8(d[im][in_], ah[im], bh[in_]);
#pragma unroll
            for (int im = 0; im < 2; im++)
#pragma unroll
                for (int in_ = 0; in_ < 8; in_++)
                    mma16n8k8(d[im][in_], ah[im], bl[in_]);
#pragma unroll
            for (int im = 0; im < 2; im++)
#pragma unroll
                for (int in_ = 0; in_ < 8; in_++)
                    mma16n8k8(d[im][in_], al[im], bh[in_]);
        }
        __syncthreads();
    }

#pragma unroll
    for (int im = 0; im < 2; im++) {
        int r0 = mBase + wm * 32 + im * 16 + g;
        int r1 = r0 + 8;
#pragma unroll
        for (int in_ = 0; in_ < 8; in_++) {
            int c = colBase + wn * 64 + in_ * 8 + 2 * tig;
            float bx = bias[c], by = bias[c + 1];
            float v0 = fmaxf(d[im][in_][0] + bx, 0.f);
            float v1 = fmaxf(d[im][in_][1] + by, 0.f);
            float v2 = fmaxf(d[im][in_][2] + bx, 0.f);
            float v3 = fmaxf(d[im][in_][3] + by, 0.f);
            if (r0 < M) *(float2*)&C[(size_t)r0 * N + c] = make_float2(v0, v1);
            if (r1 < M) *(float2*)&C[(size_t)r1 * N + c] = make_float2(v2, v3);
        }
    }
}

// ---------------- GEMM2: 128x40 tile (no N padding), double-buffered -------
#define B40 (40 * STR)
__global__ void __launch_bounds__(256)
k_mma_gemm40(const float* __restrict__ A, const float* __restrict__ Bw,
             float* __restrict__ C, int M) {
    const int K = NH, N = NC;
    extern __shared__ float sm[];
    float* As_hi = sm;
    float* As_lo = As_hi + 2 * ABUF;
    float* Bs_hi = As_lo + 2 * ABUF;
    float* Bs_lo = Bs_hi + 2 * B40;

    const int tid = threadIdx.x;
    const int wid = tid >> 5, lid = tid & 31;
    const int g = lid >> 2, tig = lid & 3;
    const int mBase = blockIdx.x * 128;

    float d[5][4];
#pragma unroll
    for (int b = 0; b < 5; b++)
#pragma unroll
        for (int c = 0; c < 4; c++) d[b][c] = 0.f;

    const int KB = K >> 5;   // 8
    float4 ra[4];
    float rb[5];
#pragma unroll
    for (int u = 0; u < 4; u++) {
        int i = tid + u * 256;
        int m = i >> 3, q = (i & 7) << 2;
        int gm = mBase + m;
        ra[u] = (gm < M) ? *(const float4*)&A[(size_t)gm * K + q]
                         : make_float4(0.f, 0.f, 0.f, 0.f);
    }
#pragma unroll
    for (int u = 0; u < 5; u++) {
        int i = tid + u * 256;
        int kc = i / 40, n = i - kc * 40;
        rb[u] = Bw[(size_t)kc * N + n];
    }

    for (int kb = 0; kb < KB; kb++) {
        const int bo = kb & 1;
        float* Ah = As_hi + bo * ABUF;
        float* Al = As_lo + bo * ABUF;
        float* Bh = Bs_hi + bo * B40;
        float* Bl = Bs_lo + bo * B40;
#pragma unroll
        for (int u = 0; u < 4; u++) {
            int i = tid + u * 256;
            int m = i >> 3, q = (i & 7) << 2;
            uint32_t h0, l0, h1, l1, h2, l2, h3, l3;
            split_tf32(ra[u].x, h0, l0); split_tf32(ra[u].y, h1, l1);
            split_tf32(ra[u].z, h2, l2); split_tf32(ra[u].w, h3, l3);
            float* ph = Ah + m * STR + q;
            float* pl = Al + m * STR + q;
            ph[0] = __uint_as_float(h0); ph[1] = __uint_as_float(h1);
            ph[2] = __uint_as_float(h2); ph[3] = __uint_as_float(h3);
            pl[0] = __uint_as_float(l0); pl[1] = __uint_as_float(l1);
            pl[2] = __uint_as_float(l2); pl[3] = __uint_as_float(l3);
        }
#pragma unroll
        for (int u = 0; u < 5; u++) {
            int i = tid + u * 256;
            int kc = i / 40, n = i - kc * 40;
            uint32_t hi, lo; split_tf32(rb[u], hi, lo);
            Bh[n * STR + kc] = __uint_as_float(hi);
            Bl[n * STR + kc] = __uint_as_float(lo);
        }
        __syncthreads();
        if (kb + 1 < KB) {
            const int kpos = (kb + 1) << 5;
#pragma unroll
            for (int u = 0; u < 4; u++) {
                int i = tid + u * 256;
                int m = i >> 3, q = (i & 7) << 2;
                int gm = mBase + m;
                ra[u] = (gm < M) ? *(const float4*)&A[(size_t)gm * K + kpos + q]
                                 : make_float4(0.f, 0.f, 0.f, 0.f);
            }
#pragma unroll
            for (int u = 0; u < 5; u++) {
                int i = tid + u * 256;
                int kc = i / 40, n = i - kc * 40;
                rb[u] = Bw[(size_t)(kpos + kc) * N + n];
            }
        }
#pragma unroll
        for (int ks = 0; ks < 4; ks++) {
            const int k0 = (ks << 3) + tig;
            uint32_t ah[4], al[4], bh[5][2], bl[5][2];
            {
                int r0 = (wid * 16 + g) * STR;
                ah[0] = __float_as_uint(Ah[r0 + k0]);
                ah[1] = __float_as_uint(Ah[r0 + 8 * STR + k0]);
                ah[2] = __float_as_uint(Ah[r0 + k0 + 4]);
                ah[3] = __float_as_uint(Ah[r0 + 8 * STR + k0 + 4]);
                al[0] = __float_as_uint(Al[r0 + k0]);
                al[1] = __float_as_uint(Al[r0 + 8 * STR + k0]);
                al[2] = __float_as_uint(Al[r0 + k0 + 4]);
                al[3] = __float_as_uint(Al[r0 + 8 * STR + k0 + 4]);
            }
#pragma unroll
            for (int in_ = 0; in_ < 5; in_++) {
                int n0 = (in_ * 8 + g) * STR;
                bh[in_][0] = __float_as_uint(Bh[n0 + k0]);
                bh[in_][1] = __float_as_uint(Bh[n0 + k0 + 4]);
                bl[in_][0] = __float_as_uint(Bl[n0 + k0]);
                bl[in_][1] = __float_as_uint(Bl[n0 + k0 + 4]);
            }
#pragma unroll
            for (int in_ = 0; in_ < 5; in_++) mma16n8k8(d[in_], ah, bh[in_]);
#pragma unroll
            for (int in_ = 0; in_ < 5; in_++) mma16n8k8(d[in_], ah, bl[in_]);
#pragma unroll
            for (int in_ = 0; in_ < 5; in_++) mma16n8k8(d[in_], al, bh[in_]);
        }
        __syncthreads();
    }

    int r0 = mBase + wid * 16 + g;
    int r1 = r0 + 8;
#pragma unroll
    for (int in_ = 0; in_ < 5; in_++) {
        int c = in_ * 8 + 2 * tig;
        if (r0 < M) *(float2*)&C[(size_t)r0 * N + c] = make_float2(d[in_][0], d[in_][1]);
        if (r1 < M) *(float2*)&C[(size_t)r1 * N + c] = make_float2(d[in_][2], d[in_][3]);
    }
}

// ------ fused layer-2 gather + b2 + log_softmax (warp per node) ------------
__global__ void k_gather_sm(float* __restrict__ out, const float* __restrict__ b2) {
    int t = blockIdx.x * blockDim.x + threadIdx.x;
    int w = t >> 5, lane = t & 31;          // grid sized so w < NN always
    const bool valid = lane < (NC / 4);     // lanes 0..9 own float4 chunks
    float ax = 0.f, ay = 0.f, az = 0.f, aw = 0.f;
    float di = g_dinv[w];
    if (valid) {
        float s2 = di * di;
        float4 a = g_g4[(size_t)w * (NC / 4) + lane];
        ax = a.x * s2; ay = a.y * s2; az = a.z * s2; aw = a.w * s2;
        int beg = g_off[w], n = g_cnt[w];
        int j = 0;
        for (; j + 2 <= n; j += 2) {
            int s0 = g_adj[beg + j], s1 = g_adj[beg + j + 1];
            float n0 = di * g_dinv[s0], n1 = di * g_dinv[s1];
            float4 v0 = g_g4[(size_t)s0 * (NC / 4) + lane];
            float4 v1 = g_g4[(size_t)s1 * (NC / 4) + lane];
            ax += v0.x * n0 + v1.x * n1; ay += v0.y * n0 + v1.y * n1;
            az += v0.z * n0 + v1.z * n1; aw += v0.w * n0 + v1.w * n1;
        }
        for (; j < n; j++) {
            int s = g_adj[beg + j];
            float nr = di * g_dinv[s];
            float4 v = g_g4[(size_t)s * (NC / 4) + lane];
            ax += v.x * nr; ay += v.y * nr; az += v.z * nr; aw += v.w * nr;
        }
        const float4 bb = ((const float4*)b2)[lane];
        ax += bb.x; ay += bb.y; az += bb.z; aw += bb.w;
    }
    // warp softmax over the 40 values (lanes >= 10 contribute neutrals)
    float m = valid ? fmaxf(fmaxf(ax, ay), fmaxf(az, aw)) : -INFINITY;
#pragma unroll
    for (int o = 16; o; o >>= 1) m = fmaxf(m, __shfl_xor_sync(0xffffffffu, m, o));
    float e = valid ? (expf(ax - m) + expf(ay - m) + expf(az - m) + expf(aw - m)) : 0.f;
#pragma unroll
    for (int o = 16; o; o >>= 1) e += __shfl_xor_sync(0xffffffffu, e, o);
    float lse = m + logf(e);
    if (valid)
        ((float4*)out)[(size_t)w * (NC / 4) + lane] =
            make_float4(ax - lse, ay - lse, az - lse, aw - lse);
}

// ---------------- launch ----------------
extern "C" void kernel_launch(void* const* d_in, const int* in_sizes, int n_in,
                              void* d_out, int out_size) {
    const float* x  = (const float*)d_in[0];
    const int*   ei = (const int*)  d_in[1];
    const int*   src = ei;
    const int*   dst = ei + NE;
    const float* W1 = (const float*)d_in[2];
    const float* b1 = (const float*)d_in[3];
    const float* W2 = (const float*)d_in[4];
    const float* b2 = (const float*)d_in[5];
    float* out = (float*)d_out;

    void *p_aggx = nullptr, *p_h = nullptr, *p_g = nullptr, *p_cnt = nullptr;
    cudaGetSymbolAddress(&p_aggx, g_aggx4);
    cudaGetSymbolAddress(&p_h,    g_h4);
    cudaGetSymbolAddress(&p_g,    g_g4);
    cudaGetSymbolAddress(&p_cnt,  g_cnt);
    float* aggx = (float*)p_aggx;
    float* h    = (float*)p_h;
    float* g    = (float*)p_g;

    const int SMEM1 = 8 * ABUF * (int)sizeof(float);                     // 147456
    const int SMEM2 = (2 * ABUF * 2 + 2 * B40 * 2) * (int)sizeof(float); //  96768
    cudaFuncSetAttribute(k_mma_gemm128,
                         cudaFuncAttributeMaxDynamicSharedMemorySize, SMEM1);
    cudaFuncSetAttribute(k_mma_gemm40,
                         cudaFuncAttributeMaxDynamicSharedMemorySize, SMEM2);

    // ---- CSR build (memset node + 5 launches) ----
    cudaMemsetAsync(p_cnt, 0, NN * sizeof(int));
    k_hist<<<(NE + 255) / 256, 256>>>(dst);            // launch 1
    k_bsum<<<NB, 256>>>();                             // launch 2
    k_bscan<<<1, 512>>>();                             // launch 3
    k_offsets<<<NB, 256>>>();                          // launch 4 (+dinv)
    k_fill<<<(NE + 255) / 256, 256>>>(src, dst);       // launch 5

    // ---- layer 1 ----
    k_gather_x<<<(NN * 32 + 255) / 256, 256>>>(x);     // launch 6 (ncu window)

    const int gridM = (NN + 127) / 128;  // 782
    {
        dim3 grid(NH / 128, gridM);      // (2, 782)
        k_mma_gemm128<<<grid, 256, SMEM1>>>(aggx, W1, b1, h, NN);
    }
    k_mma_gemm40<<<gridM, 256, SMEM2>>>(h, W2, g, NN);

    // ---- layer 2: gather + b2 + log_softmax fused, straight into d_out ----
    k_gather_sm<<<NN * 32 / 256, 256>>>(out, b2);
}